// round 9
// baseline (speedup 1.0000x reference)
#include <cuda_runtime.h>
#include <cstdint>

#define HH 256
#define WW 256
#define CC 128
#define HWSZ 65536
#define IMG (CC * HH * WW)          // 8388608 floats per frame
#define VIMG (36ull * 128 * 4096)   // transformed plane per image

// ---------------- scratch (__device__ globals; no allocations) -------------
__device__ float g_Q[2ull * IMG];
__device__ float g_KV[4ull * IMG];
__device__ float g_KVw[8ull * IMG];
__device__ float g_V[14ull * VIMG];
__device__ float g_M[14ull * VIMG];
__device__ float g_U[3ull * 36 * 128 * 128];

// ---------------- packed f32x2 helpers --------------------------------------
__device__ __forceinline__ unsigned long long pack2(float x, float y) {
    unsigned long long r;
    asm("mov.b64 %0, {%1,%2};" : "=l"(r) : "f"(x), "f"(y));
    return r;
}
__device__ __forceinline__ void unpack2(unsigned long long v, float& x, float& y) {
    asm("mov.b64 {%0,%1}, %2;" : "=f"(x), "=f"(y) : "l"(v));
}
__device__ __forceinline__ void ffma2(unsigned long long& d,
                                      unsigned long long a,
                                      unsigned long long b) {
    asm("fma.rn.f32x2 %0, %1, %2, %0;" : "+l"(d) : "l"(a), "l"(b));
}

// ---------------- cp.async helpers ------------------------------------------
__device__ __forceinline__ void cp16(uint32_t saddr, const void* g) {
    asm volatile("cp.async.cg.shared.global [%0], [%1], 16;"
                 :: "r"(saddr), "l"(g) : "memory");
}
#define CP_COMMIT() asm volatile("cp.async.commit_group;" ::: "memory")
#define CP_WAIT(n)  asm volatile("cp.async.wait_group %0;" :: "n"(n) : "memory")

__device__ __forceinline__ uint32_t smem_u32(const void* p) {
    uint32_t a;
    asm("{ .reg .u64 t; cvta.to.shared.u64 t, %1; cvt.u32.u64 %0, t; }"
        : "=r"(a) : "l"(p));
    return a;
}

// ---------------- Winograd F(4x4,3x3) transform primitives ------------------
#define BTCOMB(d0,d1,d2,d3,d4,d5,o0,o1,o2,o3,o4,o5) do {                   \
    o0 = 4.f*(d0) - 5.f*(d2) + (d4);                                       \
    float _a = (d4) - 4.f*(d2), _b = (d3) - 4.f*(d1);                      \
    o1 = _a + _b; o2 = _a - _b;                                            \
    float _c = (d4) - (d2), _e = 2.f*((d3) - (d1));                        \
    o3 = _c + _e; o4 = _c - _e;                                            \
    o5 = 4.f*(d1) - 5.f*(d3) + (d5);                                       \
} while (0)

#define ATCOMB(m0,m1,m2,m3,m4,m5,o0,o1,o2,o3) do {                         \
    float _s = (m1)+(m2), _d = (m1)-(m2), _t = (m3)+(m4), _u = (m3)-(m4);  \
    o0 = (m0) + _s + _t;                                                   \
    o1 = _d + 2.f*_u;                                                      \
    o2 = _s + 4.f*_t;                                                      \
    o3 = _d + 8.f*_u + (m5);                                               \
} while (0)

#define GCOMB(w0,w1,w2,o0,o1,o2,o3,o4,o5) do {                             \
    o0 = 0.25f*(w0);                                                       \
    float _n = -(w0) - (w2);                                               \
    o1 = (_n - (w1)) * (1.f/6.f);                                          \
    o2 = (_n + (w1)) * (1.f/6.f);                                          \
    float _p = (w0)*(1.f/24.f) + (w2)*(1.f/6.f), _q = (w1)*(1.f/12.f);     \
    o3 = _p + _q; o4 = _p - _q;                                            \
    o5 = (w2);                                                             \
} while (0)

// ---------------------------------------------------------------------------
// Filter transform, all 3 weight sets in one launch.
// ---------------------------------------------------------------------------
__global__ __launch_bounds__(256) void wino_filt3(
    const float* __restrict__ W0, const float* __restrict__ W1,
    const float* __restrict__ W2, float* __restrict__ U)
{
    int idx = blockIdx.x * 256 + threadIdx.x;
    if (idx >= 3 * 16384) return;
    int set = idx >> 14, e = idx & 16383;
    int oc = e & 127, ic = e >> 7;
    const float* W = (set == 0) ? W0 : (set == 1) ? W1 : W2;
    float* Us = U + (size_t)set * (36 * 16384);
    float w[3][3];
#pragma unroll
    for (int a = 0; a < 3; ++a)
#pragma unroll
        for (int b = 0; b < 3; ++b)
            w[a][b] = W[(size_t)oc * 1152 + ic * 9 + a * 3 + b];
    float ee[6][3];
#pragma unroll
    for (int b = 0; b < 3; ++b)
        GCOMB(w[0][b], w[1][b], w[2][b],
              ee[0][b], ee[1][b], ee[2][b], ee[3][b], ee[4][b], ee[5][b]);
#pragma unroll
    for (int i = 0; i < 6; ++i) {
        float u0, u1, u2, u3, u4, u5;
        GCOMB(ee[i][0], ee[i][1], ee[i][2], u0, u1, u2, u3, u4, u5);
        float* up = Us + (size_t)(i * 6) * 16384 + ic * 128 + oc;
        up[0 * 16384] = u0; up[1 * 16384] = u1; up[2 * 16384] = u2;
        up[3 * 16384] = u3; up[4 * 16384] = u4; up[5 * 16384] = u5;
    }
}

// ---------------------------------------------------------------------------
// Merged input transform: img z in [0,14): z<2 -> xq; z<6 -> xkv; else xkvw
// ---------------------------------------------------------------------------
__global__ __launch_bounds__(256) void wino_in14(
    const float* __restrict__ xq, const float* __restrict__ xkv,
    const float* __restrict__ xkvw, float* __restrict__ vt)
{
    __shared__ __align__(16) float s_d[4][6][264];
    int img = blockIdx.z, ty = blockIdx.y, c4 = blockIdx.x;
    int tid = threadIdx.x;
    const float* xb;
    if (img < 2)      xb = xq   + (size_t)img * IMG;
    else if (img < 6) xb = xkv  + (size_t)(img - 2) * IMG;
    else              xb = xkvw + (size_t)(img - 6) * IMG;
    xb += (size_t)(c4 * 4) * HWSZ;

    for (int i = tid; i < 4 * 6 * 258; i += 256) {
        int c = i / (6 * 258);
        int rem = i - c * (6 * 258);
        int r = rem / 258, col = rem - r * 258;
        int gy = ty * 4 - 1 + r, gx = col - 1;
        float v = 0.f;
        if ((unsigned)gy < 256u && (unsigned)gx < 256u)
            v = xb[(size_t)c * HWSZ + gy * 256 + gx];
        s_d[c][r][col] = v;
    }
    __syncthreads();

    int tx = tid & 63, c = tid >> 6;
    float d[6][6];
#pragma unroll
    for (int r = 0; r < 6; ++r) {
        const float4* row = (const float4*)s_d[c][r];
        float4 a = row[tx], b = row[tx + 1];
        d[r][0] = a.x; d[r][1] = a.y; d[r][2] = a.z;
        d[r][3] = a.w; d[r][4] = b.x; d[r][5] = b.y;
    }
    float e[6][6];
#pragma unroll
    for (int j = 0; j < 6; ++j)
        BTCOMB(d[0][j], d[1][j], d[2][j], d[3][j], d[4][j], d[5][j],
               e[0][j], e[1][j], e[2][j], e[3][j], e[4][j], e[5][j]);

    float* dst = vt + (size_t)img * VIMG + (size_t)(c4 * 4 + c) * 4096 +
                 ty * 64 + tx;
#pragma unroll
    for (int i = 0; i < 6; ++i) {
        float o0, o1, o2, o3, o4, o5;
        BTCOMB(e[i][0], e[i][1], e[i][2], e[i][3], e[i][4], e[i][5],
               o0, o1, o2, o3, o4, o5);
        float* dp = dst + (size_t)(i * 6) * 524288;
        dp[0ull * 524288] = o0; dp[1ull * 524288] = o1; dp[2ull * 524288] = o2;
        dp[3ull * 524288] = o3; dp[4ull * 524288] = o4; dp[5ull * 524288] = o5;
    }
}

// FF-stage input transform (plain, 2 images from gQ)
__global__ __launch_bounds__(256) void wino_in(
    const float* __restrict__ x, float* __restrict__ vt)
{
    __shared__ __align__(16) float s_d[4][6][264];
    int img = blockIdx.z, ty = blockIdx.y, c4 = blockIdx.x;
    int tid = threadIdx.x;
    const float* xb = x + (size_t)img * IMG + (size_t)(c4 * 4) * HWSZ;

    for (int i = tid; i < 4 * 6 * 258; i += 256) {
        int c = i / (6 * 258);
        int rem = i - c * (6 * 258);
        int r = rem / 258, col = rem - r * 258;
        int gy = ty * 4 - 1 + r, gx = col - 1;
        float v = 0.f;
        if ((unsigned)gy < 256u && (unsigned)gx < 256u)
            v = xb[(size_t)c * HWSZ + gy * 256 + gx];
        s_d[c][r][col] = v;
    }
    __syncthreads();

    int tx = tid & 63, c = tid >> 6;
    float d[6][6];
#pragma unroll
    for (int r = 0; r < 6; ++r) {
        const float4* row = (const float4*)s_d[c][r];
        float4 a = row[tx], b = row[tx + 1];
        d[r][0] = a.x; d[r][1] = a.y; d[r][2] = a.z;
        d[r][3] = a.w; d[r][4] = b.x; d[r][5] = b.y;
    }
    float e[6][6];
#pragma unroll
    for (int j = 0; j < 6; ++j)
        BTCOMB(d[0][j], d[1][j], d[2][j], d[3][j], d[4][j], d[5][j],
               e[0][j], e[1][j], e[2][j], e[3][j], e[4][j], e[5][j]);

    float* dst = vt + (size_t)img * VIMG + (size_t)(c4 * 4 + c) * 4096 +
                 ty * 64 + tx;
#pragma unroll
    for (int i = 0; i < 6; ++i) {
        float o0, o1, o2, o3, o4, o5;
        BTCOMB(e[i][0], e[i][1], e[i][2], e[i][3], e[i][4], e[i][5],
               o0, o1, o2, o3, o4, o5);
        float* dp = dst + (size_t)(i * 6) * 524288;
        dp[0ull * 524288] = o0; dp[1ull * 524288] = o1; dp[2ull * 524288] = o2;
        dp[3ull * 524288] = o3; dp[4ull * 524288] = o4; dp[5ull * 524288] = o5;
    }
}

// ---------------------------------------------------------------------------
// Winograd GEMM v3: 512 threads, block = 256 tiles x 128 oc.
// Thread = 4 tiles x 16 oc (8 f32x2 pairs). 3-stage cp.async pipeline.
// ---------------------------------------------------------------------------
__global__ __launch_bounds__(512, 1) void wino_gemm(
    const float* __restrict__ vt, const float* __restrict__ u,
    float* __restrict__ mout, int route)
{
    __shared__ __align__(16) float s_b[3][8][256];
    __shared__ __align__(16) float s_a[3][8][128];

    int pos = blockIdx.y, img = blockIdx.z, tb = blockIdx.x;
    int tid = threadIdx.x, ocs = tid >> 6, pg = tid & 63;

    int uset = route ? ((img < 2) ? 0 : 1) : 2;
    const float* B = vt + (size_t)img * VIMG + (size_t)pos * 524288 + tb * 256;
    const float* A = u + (size_t)uset * (36 * 16384) + (size_t)pos * 16384;

    uint32_t sb0 = smem_u32(&s_b[0][0][0]);
    uint32_t sa0 = smem_u32(&s_a[0][0][0]);

    // copy slots: B — 1 cp16 per thread; A — threads < 256
    int brow = tid >> 6, bcol = (tid & 63) << 2;
    int arow = (tid & 255) >> 5, acol = (tid & 31) << 2;

#define COPY_CHUNK(chunk, buf) do {                                        \
    int _ic0 = (chunk) * 8;                                                \
    cp16(sb0 + (buf) * 8192 + (brow * 256 + bcol) * 4,                     \
         B + (size_t)(_ic0 + brow) * 4096 + bcol);                         \
    if (tid < 256)                                                         \
        cp16(sa0 + (buf) * 4096 + (arow * 128 + acol) * 4,                 \
             A + (size_t)(_ic0 + arow) * 128 + acol);                      \
} while (0)

    unsigned long long acc[4][8];
#pragma unroll
    for (int p = 0; p < 4; ++p)
#pragma unroll
        for (int j = 0; j < 8; ++j) acc[p][j] = 0ull;

    COPY_CHUNK(0, 0); CP_COMMIT();
    COPY_CHUNK(1, 1); CP_COMMIT();
    COPY_CHUNK(2, 2); CP_COMMIT();

    for (int c = 0; c < 16; ++c) {
        int buf = c % 3;
        CP_WAIT(2);
        __syncthreads();

#pragma unroll
        for (int ic = 0; ic < 8; ++ic) {
            unsigned long long wv[8];
            const unsigned long long* wp =
                (const unsigned long long*)&s_a[buf][ic][ocs * 16];
#pragma unroll
            for (int j = 0; j < 8; ++j) wv[j] = wp[j];
#pragma unroll
            for (int p = 0; p < 4; ++p) {
                float iv = s_b[buf][ic][pg + (p << 6)];
                unsigned long long iv2 = pack2(iv, iv);
#pragma unroll
                for (int j = 0; j < 8; ++j) ffma2(acc[p][j], iv2, wv[j]);
            }
        }
        __syncthreads();
        if (c + 3 < 16) COPY_CHUNK(c + 3, buf);
        CP_COMMIT();   // unconditional: keeps group counting uniform
    }

    float* Mo = mout + (size_t)img * VIMG + (size_t)pos * 524288 + tb * 256;
#pragma unroll
    for (int j = 0; j < 8; ++j) {
        int oc0 = ocs * 16 + 2 * j;
#pragma unroll
        for (int p = 0; p < 4; ++p) {
            float v0, v1;
            unpack2(acc[p][j], v0, v1);
            int t = pg + (p << 6);
            Mo[(size_t)oc0 * 4096 + t] = v0;
            Mo[(size_t)(oc0 + 1) * 4096 + t] = v1;
        }
    }
#undef COPY_CHUNK
}

// ---------------------------------------------------------------------------
// Merged output transform + bias + PReLU + residual, per-image routing.
// ---------------------------------------------------------------------------
__global__ __launch_bounds__(256) void wino_out14(
    const float* __restrict__ mout,
    const float* __restrict__ r0, const float* __restrict__ r1,
    const float* __restrict__ r2,
    float* __restrict__ y0, float* __restrict__ y1, float* __restrict__ y2,
    const float* __restrict__ bias0, const float* __restrict__ alpha0,
    const float* __restrict__ bias1, const float* __restrict__ alpha1,
    int route)
{
    __shared__ __align__(16) float s_o[8][4][256];
    int img = blockIdx.z, ty = blockIdx.y, og = blockIdx.x;
    int tid = threadIdx.x;

    const float* resid; float* y; const float* bias; const float* alpha;
    if (!route || img < 2) {
        resid = r0 + (size_t)img * IMG; y = y0 + (size_t)img * IMG;
        bias = bias0; alpha = alpha0;
    } else if (img < 6) {
        resid = r1 + (size_t)(img - 2) * IMG; y = y1 + (size_t)(img - 2) * IMG;
        bias = bias1; alpha = alpha1;
    } else {
        resid = r2 + (size_t)(img - 6) * IMG; y = y2 + (size_t)(img - 6) * IMG;
        bias = bias1; alpha = alpha1;
    }

#pragma unroll
    for (int it = 0; it < 2; ++it) {
        int item = tid + it * 256;
        int tx = item & 63, ol = item >> 6;
        const float* Mp = mout + (size_t)img * VIMG +
                          (size_t)(og * 8 + ol) * 4096 + ty * 64 + tx;
        float m[6][6];
#pragma unroll
        for (int pos = 0; pos < 36; ++pos)
            m[pos / 6][pos % 6] = Mp[(size_t)pos * 524288];
        float e[4][6];
#pragma unroll
        for (int j = 0; j < 6; ++j)
            ATCOMB(m[0][j], m[1][j], m[2][j], m[3][j], m[4][j], m[5][j],
                   e[0][j], e[1][j], e[2][j], e[3][j]);
#pragma unroll
        for (int r = 0; r < 4; ++r) {
            float o0, o1, o2, o3;
            ATCOMB(e[r][0], e[r][1], e[r][2], e[r][3], e[r][4], e[r][5],
                   o0, o1, o2, o3);
            ((float4*)s_o[ol][r])[tx] = make_float4(o0, o1, o2, o3);
        }
    }
    __syncthreads();

    float a = alpha[0];
    for (int i = tid; i < 8192; i += 256) {
        int ol = i >> 10, rem = i & 1023, r = rem >> 8, px = rem & 255;
        int oc = og * 8 + ol;
        int gy = ty * 4 + r;
        size_t addr = (size_t)oc * HWSZ + gy * 256 + px;
        float v = s_o[ol][r][px] + bias[oc];
        v = (v >= 0.f) ? v : a * v;
        y[addr] = resid[addr] + v;
    }
}

// ---------------------------------------------------------------------------
// Windowed dual-branch attention (register-blocked, round-4 version)
// ---------------------------------------------------------------------------
#define QST 66
#define KST 392
#define PST 66
#define VST 133
#define OST 66
#define OFF_SK (33792 / 4)
#define OFF_SV (101376 / 4)
#define OFF_SM (169472 / 4)
#define ATTN_SMEM 169728
#define NK 384

__global__ __launch_bounds__(256) void win_attn(
    float* __restrict__ Qbuf, const float* __restrict__ KV,
    const float* __restrict__ KVw, const float* __restrict__ em)
{
    extern __shared__ __align__(16) float sm[];
    float* s_q = sm;
    float* s_k = sm + OFF_SK;
    float* s_p = sm;
    float* s_v = sm + OFF_SV;
    float* s_m = sm + OFF_SM;

    int bwin = blockIdx.x;
    int bb  = bwin >> 10;
    int wy8 = ((bwin >> 5) & 31) << 3;
    int wx8 = (bwin & 31) << 3;
    int tid = threadIdx.x;
    int qb = tid >> 5;
    int kidx = tid & 31;

    float* qimg = Qbuf + (size_t)bb * IMG;
    const float* kv0 = KV + (size_t)bb * 2 * IMG;
    const float* kv1 = KVw + (size_t)bb * 4 * IMG;

    for (int i = tid; i < 64 * CC; i += 256) {
        int q = i & 63, c = i >> 6;
        int gy = wy8 + (q >> 3), gx = wx8 + (q & 7);
        s_q[c * QST + q] = qimg[(size_t)c * HWSZ + gy * WW + gx];
    }
    if (tid < 64) {
        int gy = wy8 + (tid >> 3), gx = wx8 + (tid & 7);
        s_m[tid] = em[(size_t)bb * HWSZ + gy * WW + gx];
    }

    unsigned long long accs[4][12];
#pragma unroll
    for (int p = 0; p < 4; ++p)
#pragma unroll
        for (int j = 0; j < 12; ++j) accs[p][j] = 0ull;

    for (int c0 = 0; c0 < 128; c0 += 64) {
        __syncthreads();
        for (int i = tid; i < 64 * NK; i += 256) {
            int k = i % NK, c2 = i / NK;
            const float* base;
            int t;
            if (k < 128) { base = kv0 + (size_t)(k >> 6) * IMG; t = k & 63; }
            else { int kk = k - 128; base = kv1 + (size_t)(kk >> 6) * IMG; t = kk & 63; }
            int gy = wy8 + (t >> 3), gx = wx8 + (t & 7);
            s_k[c2 * KST + k] =
                base[(size_t)(c0 + c2) * HWSZ + gy * WW + gx];
        }
        __syncthreads();

#pragma unroll 2
        for (int c2 = 0; c2 < 64; ++c2) {
            const unsigned long long* qsrc =
                (const unsigned long long*)(s_q + (c0 + c2) * QST + qb * 8);
            unsigned long long qp0 = qsrc[0], qp1 = qsrc[1],
                               qp2 = qsrc[2], qp3 = qsrc[3];
            const float* krow = s_k + c2 * KST + kidx;
#pragma unroll
            for (int j = 0; j < 12; ++j) {
                float kv = krow[32 * j];
                unsigned long long k2 = pack2(kv, kv);
                ffma2(accs[0][j], qp0, k2);
                ffma2(accs[1][j], qp1, k2);
                ffma2(accs[2][j], qp2, k2);
                ffma2(accs[3][j], qp3, k2);
            }
        }
    }

    float sreg[8][12];
#pragma unroll
    for (int p = 0; p < 4; ++p)
#pragma unroll
        for (int j = 0; j < 12; ++j)
            unpack2(accs[p][j], sreg[2 * p][j], sreg[2 * p + 1][j]);

    const float SCALE = 0.08838834764831845f;
#pragma unroll
    for (int r = 0; r < 8; ++r) {
        float msk = s_m[qb * 8 + r];
        {
            float m = sreg[r][0];
#pragma unroll
            for (int j = 1; j < 4; ++j) m = fmaxf(m, sreg[r][j]);
#pragma unroll
            for (int off = 16; off >= 1; off >>= 1)
                m = fmaxf(m, __shfl_xor_sync(0xffffffffu, m, off));
            m *= SCALE;
            float sum = 0.f;
#pragma unroll
            for (int j = 0; j < 4; ++j) {
                float e = __expf(sreg[r][j] * SCALE - m);
                sreg[r][j] = e; sum += e;
            }
#pragma unroll
            for (int off = 16; off >= 1; off >>= 1)
                sum += __shfl_xor_sync(0xffffffffu, sum, off);
            float inv = msk / sum;
#pragma unroll
            for (int j = 0; j < 4; ++j) sreg[r][j] *= inv;
        }
        {
            float m = sreg[r][4];
#pragma unroll
            for (int j = 5; j < 12; ++j) m = fmaxf(m, sreg[r][j]);
#pragma unroll
            for (int off = 16; off >= 1; off >>= 1)
                m = fmaxf(m, __shfl_xor_sync(0xffffffffu, m, off));
            m *= SCALE;
            float sum = 0.f;
#pragma unroll
            for (int j = 4; j < 12; ++j) {
                float e = __expf(sreg[r][j] * SCALE - m);
                sreg[r][j] = e; sum += e;
            }
#pragma unroll
            for (int off = 16; off >= 1; off >>= 1)
                sum += __shfl_xor_sync(0xffffffffu, sum, off);
            float inv = (1.f - msk) / sum;
#pragma unroll
            for (int j = 4; j < 12; ++j) sreg[r][j] *= inv;
        }
    }

    __syncthreads();
#pragma unroll
    for (int j = 0; j < 12; ++j) {
        int k = kidx + 32 * j;
#pragma unroll
        for (int p = 0; p < 4; ++p)
            *(unsigned long long*)(s_p + k * PST + qb * 8 + 2 * p) =
                pack2(sreg[2 * p][j], sreg[2 * p + 1][j]);
    }

    unsigned long long oacc[4][4];
#pragma unroll
    for (int p = 0; p < 4; ++p)
#pragma unroll
        for (int jc = 0; jc < 4; ++jc) oacc[p][jc] = 0ull;

    for (int kc = 0; kc < 3; ++kc) {
        __syncthreads();
        for (int i = tid; i < 128 * CC; i += 256) {
            int kk = i & 127, c = i >> 7;
            int k = kc * 128 + kk;
            const float* base;
            int t;
            if (k < 128) { base = kv0 + (size_t)(k >> 6) * IMG; t = k & 63; }
            else { int k2 = k - 128; base = kv1 + (size_t)(k2 >> 6) * IMG; t = k2 & 63; }
            int gy = wy8 + (t >> 3), gx = wx8 + (t & 7);
            s_v[kk * VST + c] = base[(size_t)c * HWSZ + gy * WW + gx];
        }
        __syncthreads();

#pragma unroll 2
        for (int kk = 0; kk < 128; ++kk) {
            int k = kc * 128 + kk;
            const unsigned long long* pp =
                (const unsigned long long*)(s_p + k * PST + qb * 8);
            unsigned long long p0 = pp[0], p1 = pp[1], p2 = pp[2], p3 = pp[3];
            const float* vrow = s_v + kk * VST + kidx;
#pragma unroll
            for (int jc = 0; jc < 4; ++jc) {
                float v = vrow[32 * jc];
                unsigned long long v2 = pack2(v, v);
                ffma2(oacc[0][jc], p0, v2);
                ffma2(oacc[1][jc], p1, v2);
                ffma2(oacc[2][jc], p2, v2);
                ffma2(oacc[3][jc], p3, v2);
            }
        }
    }

    __syncthreads();
    float* s_o = sm;
#pragma unroll
    for (int jc = 0; jc < 4; ++jc) {
        int c = kidx + 32 * jc;
#pragma unroll
        for (int p = 0; p < 4; ++p)
            *(unsigned long long*)(s_o + c * OST + qb * 8 + 2 * p) = oacc[p][jc];
    }
    __syncthreads();
    for (int i = tid; i < 64 * CC; i += 256) {
        int q = i & 63, c = i >> 6;
        int gy = wy8 + (q >> 3), gx = wx8 + (q & 7);
        qimg[(size_t)c * HWSZ + gy * WW + gx] += s_o[c * OST + q];
    }
}

// ---------------------------------------------------------------------------
extern "C" void kernel_launch(void* const* d_in, const int* in_sizes, int n_in,
                              void* d_out, int out_size)
{
    const float* xq   = (const float*)d_in[0];
    const float* xkvw = (const float*)d_in[1];
    const float* xkv  = (const float*)d_in[2];
    const float* em   = (const float*)d_in[3];
    const float* Wq   = (const float*)d_in[4];
    const float* bq   = (const float*)d_in[5];
    const float* aq   = (const float*)d_in[6];
    const float* Wkv  = (const float*)d_in[7];
    const float* bkv  = (const float*)d_in[8];
    const float* akv  = (const float*)d_in[9];
    const float* Wff  = (const float*)d_in[10];
    const float* bff  = (const float*)d_in[11];
    const float* aff  = (const float*)d_in[12];
    float* out = (float*)d_out;

    float *gQ = nullptr, *gKV = nullptr, *gKVw = nullptr;
    float *gV = nullptr, *gM = nullptr, *gU = nullptr;
    cudaGetSymbolAddress((void**)&gQ,   g_Q);
    cudaGetSymbolAddress((void**)&gKV,  g_KV);
    cudaGetSymbolAddress((void**)&gKVw, g_KVw);
    cudaGetSymbolAddress((void**)&gV,   g_V);
    cudaGetSymbolAddress((void**)&gM,   g_M);
    cudaGetSymbolAddress((void**)&gU,   g_U);

    cudaFuncSetAttribute(win_attn, cudaFuncAttributeMaxDynamicSharedMemorySize,
                         ATTN_SMEM);

    dim3 blk(256);

    wino_filt3<<<192, blk>>>(Wq, Wkv, Wff, gU);

    wino_in14<<<dim3(32, 64, 14), blk>>>(xq, xkv, xkvw, gV);
    wino_gemm<<<dim3(16, 36, 14), 512>>>(gV, gU, gM, 1);
    wino_out14<<<dim3(16, 64, 14), blk>>>(gM, xq, xkv, xkvw, gQ, gKV, gKVw,
                                          bq, aq, bkv, akv, 1);

    win_attn<<<2048, blk, ATTN_SMEM>>>(gQ, gKV, gKVw, em);

    wino_in<<<dim3(32, 64, 2), blk>>>(gQ, gV);
    wino_gemm<<<dim3(16, 36, 2), 512>>>(gV, gU, gM, 0);
    wino_out14<<<dim3(16, 64, 2), blk>>>(gM, gQ, gQ, gQ, out, out, out,
                                         bff, aff, bff, aff, 0);
}

// round 10
// speedup vs baseline: 1.0393x; 1.0393x over previous
#include <cuda_runtime.h>
#include <cstdint>

#define HH 256
#define WW 256
#define CC 128
#define HWSZ 65536
#define IMG (CC * HH * WW)          // 8388608 floats per frame
#define VIMG (36ull * 128 * 4096)   // transformed plane per image

// ---------------- scratch (__device__ globals; no allocations) -------------
__device__ float g_Q[2ull * IMG];
__device__ float g_KV[4ull * IMG];
__device__ float g_KVw[8ull * IMG];
__device__ float g_V[14ull * VIMG];
__device__ float g_M[14ull * VIMG];
__device__ float g_U[3ull * 36 * 128 * 128];

// ---------------- packed f32x2 helpers --------------------------------------
__device__ __forceinline__ unsigned long long pack2(float x, float y) {
    unsigned long long r;
    asm("mov.b64 %0, {%1,%2};" : "=l"(r) : "f"(x), "f"(y));
    return r;
}
__device__ __forceinline__ void unpack2(unsigned long long v, float& x, float& y) {
    asm("mov.b64 {%0,%1}, %2;" : "=f"(x), "=f"(y) : "l"(v));
}
__device__ __forceinline__ void ffma2(unsigned long long& d,
                                      unsigned long long a,
                                      unsigned long long b) {
    asm("fma.rn.f32x2 %0, %1, %2, %0;" : "+l"(d) : "l"(a), "l"(b));
}

// ---------------- cp.async helpers ------------------------------------------
__device__ __forceinline__ void cp16(uint32_t saddr, const void* g) {
    asm volatile("cp.async.cg.shared.global [%0], [%1], 16;"
                 :: "r"(saddr), "l"(g) : "memory");
}
#define CP_COMMIT() asm volatile("cp.async.commit_group;" ::: "memory")
#define CP_WAIT(n)  asm volatile("cp.async.wait_group %0;" :: "n"(n) : "memory")

__device__ __forceinline__ uint32_t smem_u32(const void* p) {
    uint32_t a;
    asm("{ .reg .u64 t; cvta.to.shared.u64 t, %1; cvt.u32.u64 %0, t; }"
        : "=r"(a) : "l"(p));
    return a;
}

// ---------------- Winograd F(4x4,3x3) transform primitives ------------------
#define BTCOMB(d0,d1,d2,d3,d4,d5,o0,o1,o2,o3,o4,o5) do {                   \
    o0 = 4.f*(d0) - 5.f*(d2) + (d4);                                       \
    float _a = (d4) - 4.f*(d2), _b = (d3) - 4.f*(d1);                      \
    o1 = _a + _b; o2 = _a - _b;                                            \
    float _c = (d4) - (d2), _e = 2.f*((d3) - (d1));                        \
    o3 = _c + _e; o4 = _c - _e;                                            \
    o5 = 4.f*(d1) - 5.f*(d3) + (d5);                                       \
} while (0)

#define ATCOMB(m0,m1,m2,m3,m4,m5,o0,o1,o2,o3) do {                         \
    float _s = (m1)+(m2), _d = (m1)-(m2), _t = (m3)+(m4), _u = (m3)-(m4);  \
    o0 = (m0) + _s + _t;                                                   \
    o1 = _d + 2.f*_u;                                                      \
    o2 = _s + 4.f*_t;                                                      \
    o3 = _d + 8.f*_u + (m5);                                               \
} while (0)

#define GCOMB(w0,w1,w2,o0,o1,o2,o3,o4,o5) do {                             \
    o0 = 0.25f*(w0);                                                       \
    float _n = -(w0) - (w2);                                               \
    o1 = (_n - (w1)) * (1.f/6.f);                                          \
    o2 = (_n + (w1)) * (1.f/6.f);                                          \
    float _p = (w0)*(1.f/24.f) + (w2)*(1.f/6.f), _q = (w1)*(1.f/12.f);     \
    o3 = _p + _q; o4 = _p - _q;                                            \
    o5 = (w2);                                                             \
} while (0)

// ---------------------------------------------------------------------------
// Filter transform, all 3 weight sets in one launch.
// ---------------------------------------------------------------------------
__global__ __launch_bounds__(256) void wino_filt3(
    const float* __restrict__ W0, const float* __restrict__ W1,
    const float* __restrict__ W2, float* __restrict__ U)
{
    int idx = blockIdx.x * 256 + threadIdx.x;
    if (idx >= 3 * 16384) return;
    int set = idx >> 14, e = idx & 16383;
    int oc = e & 127, ic = e >> 7;
    const float* W = (set == 0) ? W0 : (set == 1) ? W1 : W2;
    float* Us = U + (size_t)set * (36 * 16384);
    float w[3][3];
#pragma unroll
    for (int a = 0; a < 3; ++a)
#pragma unroll
        for (int b = 0; b < 3; ++b)
            w[a][b] = W[(size_t)oc * 1152 + ic * 9 + a * 3 + b];
    float ee[6][3];
#pragma unroll
    for (int b = 0; b < 3; ++b)
        GCOMB(w[0][b], w[1][b], w[2][b],
              ee[0][b], ee[1][b], ee[2][b], ee[3][b], ee[4][b], ee[5][b]);
#pragma unroll
    for (int i = 0; i < 6; ++i) {
        float u0, u1, u2, u3, u4, u5;
        GCOMB(ee[i][0], ee[i][1], ee[i][2], u0, u1, u2, u3, u4, u5);
        float* up = Us + (size_t)(i * 6) * 16384 + ic * 128 + oc;
        up[0 * 16384] = u0; up[1 * 16384] = u1; up[2 * 16384] = u2;
        up[3 * 16384] = u3; up[4 * 16384] = u4; up[5 * 16384] = u5;
    }
}

// ---------------------------------------------------------------------------
// Merged input transform: img z in [0,14): z<2 -> xq; z<6 -> xkv; else xkvw
// ---------------------------------------------------------------------------
__global__ __launch_bounds__(256) void wino_in14(
    const float* __restrict__ xq, const float* __restrict__ xkv,
    const float* __restrict__ xkvw, float* __restrict__ vt)
{
    __shared__ __align__(16) float s_d[4][6][264];
    int img = blockIdx.z, ty = blockIdx.y, c4 = blockIdx.x;
    int tid = threadIdx.x;
    const float* xb;
    if (img < 2)      xb = xq   + (size_t)img * IMG;
    else if (img < 6) xb = xkv  + (size_t)(img - 2) * IMG;
    else              xb = xkvw + (size_t)(img - 6) * IMG;
    xb += (size_t)(c4 * 4) * HWSZ;

    for (int i = tid; i < 4 * 6 * 258; i += 256) {
        int c = i / (6 * 258);
        int rem = i - c * (6 * 258);
        int r = rem / 258, col = rem - r * 258;
        int gy = ty * 4 - 1 + r, gx = col - 1;
        float v = 0.f;
        if ((unsigned)gy < 256u && (unsigned)gx < 256u)
            v = xb[(size_t)c * HWSZ + gy * 256 + gx];
        s_d[c][r][col] = v;
    }
    __syncthreads();

    int tx = tid & 63, c = tid >> 6;
    float d[6][6];
#pragma unroll
    for (int r = 0; r < 6; ++r) {
        const float4* row = (const float4*)s_d[c][r];
        float4 a = row[tx], b = row[tx + 1];
        d[r][0] = a.x; d[r][1] = a.y; d[r][2] = a.z;
        d[r][3] = a.w; d[r][4] = b.x; d[r][5] = b.y;
    }
    float e[6][6];
#pragma unroll
    for (int j = 0; j < 6; ++j)
        BTCOMB(d[0][j], d[1][j], d[2][j], d[3][j], d[4][j], d[5][j],
               e[0][j], e[1][j], e[2][j], e[3][j], e[4][j], e[5][j]);

    float* dst = vt + (size_t)img * VIMG + (size_t)(c4 * 4 + c) * 4096 +
                 ty * 64 + tx;
#pragma unroll
    for (int i = 0; i < 6; ++i) {
        float o0, o1, o2, o3, o4, o5;
        BTCOMB(e[i][0], e[i][1], e[i][2], e[i][3], e[i][4], e[i][5],
               o0, o1, o2, o3, o4, o5);
        float* dp = dst + (size_t)(i * 6) * 524288;
        dp[0ull * 524288] = o0; dp[1ull * 524288] = o1; dp[2ull * 524288] = o2;
        dp[3ull * 524288] = o3; dp[4ull * 524288] = o4; dp[5ull * 524288] = o5;
    }
}

// FF-stage input transform (plain, 2 images from gQ)
__global__ __launch_bounds__(256) void wino_in(
    const float* __restrict__ x, float* __restrict__ vt)
{
    __shared__ __align__(16) float s_d[4][6][264];
    int img = blockIdx.z, ty = blockIdx.y, c4 = blockIdx.x;
    int tid = threadIdx.x;
    const float* xb = x + (size_t)img * IMG + (size_t)(c4 * 4) * HWSZ;

    for (int i = tid; i < 4 * 6 * 258; i += 256) {
        int c = i / (6 * 258);
        int rem = i - c * (6 * 258);
        int r = rem / 258, col = rem - r * 258;
        int gy = ty * 4 - 1 + r, gx = col - 1;
        float v = 0.f;
        if ((unsigned)gy < 256u && (unsigned)gx < 256u)
            v = xb[(size_t)c * HWSZ + gy * 256 + gx];
        s_d[c][r][col] = v;
    }
    __syncthreads();

    int tx = tid & 63, c = tid >> 6;
    float d[6][6];
#pragma unroll
    for (int r = 0; r < 6; ++r) {
        const float4* row = (const float4*)s_d[c][r];
        float4 a = row[tx], b = row[tx + 1];
        d[r][0] = a.x; d[r][1] = a.y; d[r][2] = a.z;
        d[r][3] = a.w; d[r][4] = b.x; d[r][5] = b.y;
    }
    float e[6][6];
#pragma unroll
    for (int j = 0; j < 6; ++j)
        BTCOMB(d[0][j], d[1][j], d[2][j], d[3][j], d[4][j], d[5][j],
               e[0][j], e[1][j], e[2][j], e[3][j], e[4][j], e[5][j]);

    float* dst = vt + (size_t)img * VIMG + (size_t)(c4 * 4 + c) * 4096 +
                 ty * 64 + tx;
#pragma unroll
    for (int i = 0; i < 6; ++i) {
        float o0, o1, o2, o3, o4, o5;
        BTCOMB(e[i][0], e[i][1], e[i][2], e[i][3], e[i][4], e[i][5],
               o0, o1, o2, o3, o4, o5);
        float* dp = dst + (size_t)(i * 6) * 524288;
        dp[0ull * 524288] = o0; dp[1ull * 524288] = o1; dp[2ull * 524288] = o2;
        dp[3ull * 524288] = o3; dp[4ull * 524288] = o4; dp[5ull * 524288] = o5;
    }
}

// ---------------------------------------------------------------------------
// Winograd GEMM (R7/R8 best version): 256 threads, block = 256 tiles x 128 oc.
// Thread = 4 tiles x 32 oc (16 f32x2 pairs). cp.async 2-stage.
// ---------------------------------------------------------------------------
__global__ __launch_bounds__(256, 1) void wino_gemm(
    const float* __restrict__ vt, const float* __restrict__ u,
    float* __restrict__ mout, int route)
{
    __shared__ __align__(16) float s_b[2][8][256];
    __shared__ __align__(16) float s_a[2][8][128];

    int pos = blockIdx.y, img = blockIdx.z, tb = blockIdx.x;
    int tid = threadIdx.x, ocs = tid >> 6, pg = tid & 63;

    int uset = route ? ((img < 2) ? 0 : 1) : 2;
    const float* B = vt + (size_t)img * VIMG + (size_t)pos * 524288 + tb * 256;
    const float* A = u + (size_t)uset * (36 * 16384) + (size_t)pos * 16384;

    uint32_t sb0 = smem_u32(&s_b[0][0][0]);
    uint32_t sa0 = smem_u32(&s_a[0][0][0]);

    int brow0 = tid >> 6, bcol0 = (tid & 63) << 2;
    int brow1 = 4 + (tid >> 6), bcol1 = bcol0;
    int arow = tid >> 5, acol = (tid & 31) << 2;

#define COPY_CHUNK(chunk, buf) do {                                        \
    int _ic0 = (chunk) * 8;                                                \
    cp16(sb0 + (buf) * 8192 + (brow0 * 256 + bcol0) * 4,                   \
         B + (size_t)(_ic0 + brow0) * 4096 + bcol0);                       \
    cp16(sb0 + (buf) * 8192 + (brow1 * 256 + bcol1) * 4,                   \
         B + (size_t)(_ic0 + brow1) * 4096 + bcol1);                       \
    cp16(sa0 + (buf) * 4096 + (arow * 128 + acol) * 4,                     \
         A + (size_t)(_ic0 + arow) * 128 + acol);                          \
    CP_COMMIT();                                                           \
} while (0)

    unsigned long long acc[4][16];
#pragma unroll
    for (int p = 0; p < 4; ++p)
#pragma unroll
        for (int j = 0; j < 16; ++j) acc[p][j] = 0ull;

    COPY_CHUNK(0, 0);

    for (int c = 0; c < 16; ++c) {
        int buf = c & 1;
        if (c < 15) {
            COPY_CHUNK(c + 1, buf ^ 1);
            CP_WAIT(1);
        } else {
            CP_WAIT(0);
        }
        __syncthreads();

#pragma unroll
        for (int ic = 0; ic < 8; ++ic) {
            unsigned long long wv[16];
            const unsigned long long* wp =
                (const unsigned long long*)&s_a[buf][ic][ocs * 32];
#pragma unroll
            for (int j = 0; j < 16; ++j) wv[j] = wp[j];
#pragma unroll
            for (int p = 0; p < 4; ++p) {
                float iv = s_b[buf][ic][pg + (p << 6)];
                unsigned long long iv2 = pack2(iv, iv);
#pragma unroll
                for (int j = 0; j < 16; ++j) ffma2(acc[p][j], iv2, wv[j]);
            }
        }
        __syncthreads();
    }

    float* Mo = mout + (size_t)img * VIMG + (size_t)pos * 524288 + tb * 256;
#pragma unroll
    for (int j = 0; j < 16; ++j) {
        int oc0 = ocs * 32 + 2 * j;
#pragma unroll
        for (int p = 0; p < 4; ++p) {
            float v0, v1;
            unpack2(acc[p][j], v0, v1);
            int t = pg + (p << 6);
            Mo[(size_t)oc0 * 4096 + t] = v0;
            Mo[(size_t)(oc0 + 1) * 4096 + t] = v1;
        }
    }
#undef COPY_CHUNK
}

// ---------------------------------------------------------------------------
// Merged output transform + bias + PReLU + residual, per-image routing.
// ---------------------------------------------------------------------------
__global__ __launch_bounds__(256) void wino_out14(
    const float* __restrict__ mout,
    const float* __restrict__ r0, const float* __restrict__ r1,
    const float* __restrict__ r2,
    float* __restrict__ y0, float* __restrict__ y1, float* __restrict__ y2,
    const float* __restrict__ bias0, const float* __restrict__ alpha0,
    const float* __restrict__ bias1, const float* __restrict__ alpha1,
    int route)
{
    __shared__ __align__(16) float s_o[8][4][256];
    int img = blockIdx.z, ty = blockIdx.y, og = blockIdx.x;
    int tid = threadIdx.x;

    const float* resid; float* y; const float* bias; const float* alpha;
    if (!route || img < 2) {
        resid = r0 + (size_t)img * IMG; y = y0 + (size_t)img * IMG;
        bias = bias0; alpha = alpha0;
    } else if (img < 6) {
        resid = r1 + (size_t)(img - 2) * IMG; y = y1 + (size_t)(img - 2) * IMG;
        bias = bias1; alpha = alpha1;
    } else {
        resid = r2 + (size_t)(img - 6) * IMG; y = y2 + (size_t)(img - 6) * IMG;
        bias = bias1; alpha = alpha1;
    }

#pragma unroll
    for (int it = 0; it < 2; ++it) {
        int item = tid + it * 256;
        int tx = item & 63, ol = item >> 6;
        const float* Mp = mout + (size_t)img * VIMG +
                          (size_t)(og * 8 + ol) * 4096 + ty * 64 + tx;
        float m[6][6];
#pragma unroll
        for (int pos = 0; pos < 36; ++pos)
            m[pos / 6][pos % 6] = Mp[(size_t)pos * 524288];
        float e[4][6];
#pragma unroll
        for (int j = 0; j < 6; ++j)
            ATCOMB(m[0][j], m[1][j], m[2][j], m[3][j], m[4][j], m[5][j],
                   e[0][j], e[1][j], e[2][j], e[3][j]);
#pragma unroll
        for (int r = 0; r < 4; ++r) {
            float o0, o1, o2, o3;
            ATCOMB(e[r][0], e[r][1], e[r][2], e[r][3], e[r][4], e[r][5],
                   o0, o1, o2, o3);
            ((float4*)s_o[ol][r])[tx] = make_float4(o0, o1, o2, o3);
        }
    }
    __syncthreads();

    float a = alpha[0];
    for (int i = tid; i < 8192; i += 256) {
        int ol = i >> 10, rem = i & 1023, r = rem >> 8, px = rem & 255;
        int oc = og * 8 + ol;
        int gy = ty * 4 + r;
        size_t addr = (size_t)oc * HWSZ + gy * 256 + px;
        float v = s_o[ol][r][px] + bias[oc];
        v = (v >= 0.f) ? v : a * v;
        y[addr] = resid[addr] + v;
    }
}

// ---------------------------------------------------------------------------
// Windowed dual-branch attention v3: K and V stored in smem PRE-DUPLICATED
// as (v,v) float2 so inner loops issue no pack instructions.
// Phase 1 (QK): s_q [128c][66], s_kd [32c][385 k-dup ull], 4 chunks of 32 c.
// Phase 2 (PV): s_p [384k][66], s_v2 [64k][129 c-dup ull], 6 chunks of 64 k.
// ---------------------------------------------------------------------------
#define QST 66
#define KDST 385
#define PST 66
#define VDST 129
#define OST 66
#define OFF_KD 8448      // floats
#define OFF_SV2 25344    // floats
#define OFF_SM 41856     // floats
#define ATTN_SMEM 167680
#define NK 384

__global__ __launch_bounds__(256) void win_attn(
    float* __restrict__ Qbuf, const float* __restrict__ KV,
    const float* __restrict__ KVw, const float* __restrict__ em)
{
    extern __shared__ __align__(16) float sm[];
    float* s_q = sm;
    unsigned long long* s_kd = (unsigned long long*)(sm + OFF_KD);
    float* s_p = sm;
    unsigned long long* s_v2 = (unsigned long long*)(sm + OFF_SV2);
    float* s_m = sm + OFF_SM;

    int bwin = blockIdx.x;
    int bb  = bwin >> 10;
    int wy8 = ((bwin >> 5) & 31) << 3;
    int wx8 = (bwin & 31) << 3;
    int tid = threadIdx.x;
    int qb = tid >> 5;
    int kidx = tid & 31;

    float* qimg = Qbuf + (size_t)bb * IMG;
    const float* kv0 = KV + (size_t)bb * 2 * IMG;
    const float* kv1 = KVw + (size_t)bb * 4 * IMG;

    // Q^T [c][q] and mask
    for (int i = tid; i < 64 * CC; i += 256) {
        int q = i & 63, c = i >> 6;
        int gy = wy8 + (q >> 3), gx = wx8 + (q & 7);
        s_q[c * QST + q] = qimg[(size_t)c * HWSZ + gy * WW + gx];
    }
    if (tid < 64) {
        int gy = wy8 + (tid >> 3), gx = wx8 + (tid & 7);
        s_m[tid] = em[(size_t)bb * HWSZ + gy * WW + gx];
    }

    // ================= QK: S[64q x 384k], 4 chunks of 32 channels ===========
    unsigned long long accs[4][12];
#pragma unroll
    for (int p = 0; p < 4; ++p)
#pragma unroll
        for (int j = 0; j < 12; ++j) accs[p][j] = 0ull;

    for (int c0 = 0; c0 < 128; c0 += 32) {
        __syncthreads();
        for (int i = tid; i < 32 * NK; i += 256) {
            int k = i % NK, c2 = i / NK;
            const float* base;
            int t;
            if (k < 128) { base = kv0 + (size_t)(k >> 6) * IMG; t = k & 63; }
            else { int kk = k - 128; base = kv1 + (size_t)(kk >> 6) * IMG; t = kk & 63; }
            int gy = wy8 + (t >> 3), gx = wx8 + (t & 7);
            float kvv = base[(size_t)(c0 + c2) * HWSZ + gy * WW + gx];
            s_kd[c2 * KDST + k] = pack2(kvv, kvv);
        }
        __syncthreads();

#pragma unroll 2
        for (int c2 = 0; c2 < 32; ++c2) {
            const unsigned long long* qsrc =
                (const unsigned long long*)(s_q + (c0 + c2) * QST + qb * 8);
            unsigned long long qp0 = qsrc[0], qp1 = qsrc[1],
                               qp2 = qsrc[2], qp3 = qsrc[3];
            const unsigned long long* krow = s_kd + c2 * KDST + kidx;
#pragma unroll
            for (int j = 0; j < 12; ++j) {
                unsigned long long k2 = krow[32 * j];
                ffma2(accs[0][j], qp0, k2);
                ffma2(accs[1][j], qp1, k2);
                ffma2(accs[2][j], qp2, k2);
                ffma2(accs[3][j], qp3, k2);
            }
        }
    }

    // ================= softmax in registers (per q row) =====================
    float sreg[8][12];
#pragma unroll
    for (int p = 0; p < 4; ++p)
#pragma unroll
        for (int j = 0; j < 12; ++j)
            unpack2(accs[p][j], sreg[2 * p][j], sreg[2 * p + 1][j]);

    const float SCALE = 0.08838834764831845f;
#pragma unroll
    for (int r = 0; r < 8; ++r) {
        float msk = s_m[qb * 8 + r];
        {
            float m = sreg[r][0];
#pragma unroll
            for (int j = 1; j < 4; ++j) m = fmaxf(m, sreg[r][j]);
#pragma unroll
            for (int off = 16; off >= 1; off >>= 1)
                m = fmaxf(m, __shfl_xor_sync(0xffffffffu, m, off));
            m *= SCALE;
            float sum = 0.f;
#pragma unroll
            for (int j = 0; j < 4; ++j) {
                float e = __expf(sreg[r][j] * SCALE - m);
                sreg[r][j] = e; sum += e;
            }
#pragma unroll
            for (int off = 16; off >= 1; off >>= 1)
                sum += __shfl_xor_sync(0xffffffffu, sum, off);
            float inv = msk / sum;
#pragma unroll
            for (int j = 0; j < 4; ++j) sreg[r][j] *= inv;
        }
        {
            float m = sreg[r][4];
#pragma unroll
            for (int j = 5; j < 12; ++j) m = fmaxf(m, sreg[r][j]);
#pragma unroll
            for (int off = 16; off >= 1; off >>= 1)
                m = fmaxf(m, __shfl_xor_sync(0xffffffffu, m, off));
            m *= SCALE;
            float sum = 0.f;
#pragma unroll
            for (int j = 4; j < 12; ++j) {
                float e = __expf(sreg[r][j] * SCALE - m);
                sreg[r][j] = e; sum += e;
            }
#pragma unroll
            for (int off = 16; off >= 1; off >>= 1)
                sum += __shfl_xor_sync(0xffffffffu, sum, off);
            float inv = (1.f - msk) / sum;
#pragma unroll
            for (int j = 4; j < 12; ++j) sreg[r][j] *= inv;
        }
    }

    // ---- write P to smem as [k][q]
    __syncthreads();
#pragma unroll
    for (int j = 0; j < 12; ++j) {
        int k = kidx + 32 * j;
#pragma unroll
        for (int p = 0; p < 4; ++p)
            *(unsigned long long*)(s_p + k * PST + qb * 8 + 2 * p) =
                pack2(sreg[2 * p][j], sreg[2 * p + 1][j]);
    }

    // ================= PV: O[64q x 128c], 6 chunks of 64 k ==================
    unsigned long long oacc[4][4];
#pragma unroll
    for (int p = 0; p < 4; ++p)
#pragma unroll
        for (int jc = 0; jc < 4; ++jc) oacc[p][jc] = 0ull;

    for (int kc = 0; kc < 6; ++kc) {
        __syncthreads();
        for (int i = tid; i < 64 * CC; i += 256) {
            int kk = i & 63, c = i >> 6;
            int k = kc * 64 + kk;
            const float* base;
            if (k < 128) base = kv0 + (size_t)(k >> 6) * IMG;
            else         base = kv1 + (size_t)((k - 128) >> 6) * IMG;
            int gy = wy8 + (kk >> 3), gx = wx8 + (kk & 7);
            float vv = base[(size_t)c * HWSZ + gy * WW + gx];
            s_v2[kk * VDST + c] = pack2(vv, vv);
        }
        __syncthreads();

#pragma unroll 2
        for (int kk = 0; kk < 64; ++kk) {
            int k = kc * 64 + kk;
            const unsigned long long* pp =
                (const unsigned long long*)(s_p + k * PST + qb * 8);
            unsigned long long p0 = pp[0], p1 = pp[1], p2 = pp[2], p3 = pp[3];
            const unsigned long long* vrow = s_v2 + kk * VDST + kidx;
#pragma unroll
            for (int jc = 0; jc < 4; ++jc) {
                unsigned long long v2 = vrow[32 * jc];
                ffma2(oacc[0][jc], p0, v2);
                ffma2(oacc[1][jc], p1, v2);
                ffma2(oacc[2][jc], p2, v2);
                ffma2(oacc[3][jc], p3, v2);
            }
        }
    }

    // ---- transpose O through smem, residual RMW
    __syncthreads();
    float* s_o = sm;
#pragma unroll
    for (int jc = 0; jc < 4; ++jc) {
        int c = kidx + 32 * jc;
#pragma unroll
        for (int p = 0; p < 4; ++p)
            *(unsigned long long*)(s_o + c * OST + qb * 8 + 2 * p) = oacc[p][jc];
    }
    __syncthreads();
    for (int i = tid; i < 64 * CC; i += 256) {
        int q = i & 63, c = i >> 6;
        int gy = wy8 + (q >> 3), gx = wx8 + (q & 7);
        qimg[(size_t)c * HWSZ + gy * WW + gx] += s_o[c * OST + q];
    }
}

// ---------------------------------------------------------------------------
extern "C" void kernel_launch(void* const* d_in, const int* in_sizes, int n_in,
                              void* d_out, int out_size)
{
    const float* xq   = (const float*)d_in[0];
    const float* xkvw = (const float*)d_in[1];
    const float* xkv  = (const float*)d_in[2];
    const float* em   = (const float*)d_in[3];
    const float* Wq   = (const float*)d_in[4];
    const float* bq   = (const float*)d_in[5];
    const float* aq   = (const float*)d_in[6];
    const float* Wkv  = (const float*)d_in[7];
    const float* bkv  = (const float*)d_in[8];
    const float* akv  = (const float*)d_in[9];
    const float* Wff  = (const float*)d_in[10];
    const float* bff  = (const float*)d_in[11];
    const float* aff  = (const float*)d_in[12];
    float* out = (float*)d_out;

    float *gQ = nullptr, *gKV = nullptr, *gKVw = nullptr;
    float *gV = nullptr, *gM = nullptr, *gU = nullptr;
    cudaGetSymbolAddress((void**)&gQ,   g_Q);
    cudaGetSymbolAddress((void**)&gKV,  g_KV);
    cudaGetSymbolAddress((void**)&gKVw, g_KVw);
    cudaGetSymbolAddress((void**)&gV,   g_V);
    cudaGetSymbolAddress((void**)&gM,   g_M);
    cudaGetSymbolAddress((void**)&gU,   g_U);

    cudaFuncSetAttribute(win_attn, cudaFuncAttributeMaxDynamicSharedMemorySize,
                         ATTN_SMEM);

    dim3 blk(256);

    wino_filt3<<<192, blk>>>(Wq, Wkv, Wff, gU);

    wino_in14<<<dim3(32, 64, 14), blk>>>(xq, xkv, xkvw, gV);
    wino_gemm<<<dim3(16, 36, 14), blk>>>(gV, gU, gM, 1);
    wino_out14<<<dim3(16, 64, 14), blk>>>(gM, xq, xkv, xkvw, gQ, gKV, gKVw,
                                          bq, aq, bkv, akv, 1);

    win_attn<<<2048, blk, ATTN_SMEM>>>(gQ, gKV, gKVw, em);

    wino_in<<<dim3(32, 64, 2), blk>>>(gQ, gV);
    wino_gemm<<<dim3(16, 36, 2), blk>>>(gV, gU, gM, 0);
    wino_out14<<<dim3(16, 64, 2), blk>>>(gM, gQ, gQ, gQ, out, out, out,
                                         bff, aff, bff, aff, 0);
}

// round 11
// speedup vs baseline: 1.2015x; 1.1561x over previous
#include <cuda_runtime.h>
#include <cuda_bf16.h>
#include <cstdint>

#define HH 256
#define WW 256
#define CC 128
#define HWSZ 65536
#define IMG (CC * HH * WW)          // 8388608 floats per frame
#define VIMG (36ull * 128 * 4096)   // transformed plane per image (elems)

// ---------------- scratch (__device__ globals; no allocations) -------------
__device__ float g_Q[2ull * IMG];
__device__ float g_KV[4ull * IMG];
__device__ float g_KVw[8ull * IMG];
__device__ float g_V[14ull * VIMG];      // reused as 2 bf16 planes (hi, lo)
__device__ float g_M[14ull * VIMG];
__device__ float g_U[3ull * 36 * 128 * 128];  // reused as 2 bf16 planes

// ---------------- packed f32x2 helpers --------------------------------------
__device__ __forceinline__ unsigned long long pack2(float x, float y) {
    unsigned long long r;
    asm("mov.b64 %0, {%1,%2};" : "=l"(r) : "f"(x), "f"(y));
    return r;
}
__device__ __forceinline__ void unpack2(unsigned long long v, float& x, float& y) {
    asm("mov.b64 {%0,%1}, %2;" : "=f"(x), "=f"(y) : "l"(v));
}
__device__ __forceinline__ void ffma2(unsigned long long& d,
                                      unsigned long long a,
                                      unsigned long long b) {
    asm("fma.rn.f32x2 %0, %1, %2, %0;" : "+l"(d) : "l"(a), "l"(b));
}

// ---------------- cp.async / ldmatrix / mma helpers -------------------------
__device__ __forceinline__ void cp16(uint32_t saddr, const void* g) {
    asm volatile("cp.async.cg.shared.global [%0], [%1], 16;"
                 :: "r"(saddr), "l"(g) : "memory");
}
#define CP_COMMIT() asm volatile("cp.async.commit_group;" ::: "memory")
#define CP_WAIT(n)  asm volatile("cp.async.wait_group %0;" :: "n"(n) : "memory")

__device__ __forceinline__ uint32_t smem_u32(const void* p) {
    uint32_t a;
    asm("{ .reg .u64 t; cvta.to.shared.u64 t, %1; cvt.u32.u64 %0, t; }"
        : "=r"(a) : "l"(p));
    return a;
}
__device__ __forceinline__ void ldsm4(uint32_t* r, uint32_t a) {
    asm volatile("ldmatrix.sync.aligned.m8n8.x4.shared.b16 {%0,%1,%2,%3}, [%4];"
        : "=r"(r[0]), "=r"(r[1]), "=r"(r[2]), "=r"(r[3]) : "r"(a));
}
__device__ __forceinline__ void ldsm4t(uint32_t* r, uint32_t a) {
    asm volatile("ldmatrix.sync.aligned.m8n8.x4.trans.shared.b16 {%0,%1,%2,%3}, [%4];"
        : "=r"(r[0]), "=r"(r[1]), "=r"(r[2]), "=r"(r[3]) : "r"(a));
}
__device__ __forceinline__ void mma_bf16(float* d, const uint32_t* a,
                                         uint32_t b0, uint32_t b1) {
    asm volatile(
        "mma.sync.aligned.m16n8k16.row.col.f32.bf16.bf16.f32 "
        "{%0,%1,%2,%3}, {%4,%5,%6,%7}, {%8,%9}, {%0,%1,%2,%3};"
        : "+f"(d[0]), "+f"(d[1]), "+f"(d[2]), "+f"(d[3])
        : "r"(a[0]), "r"(a[1]), "r"(a[2]), "r"(a[3]), "r"(b0), "r"(b1));
}

// ---------------- Winograd F(4x4,3x3) transform primitives ------------------
#define BTCOMB(d0,d1,d2,d3,d4,d5,o0,o1,o2,o3,o4,o5) do {                   \
    o0 = 4.f*(d0) - 5.f*(d2) + (d4);                                       \
    float _a = (d4) - 4.f*(d2), _b = (d3) - 4.f*(d1);                      \
    o1 = _a + _b; o2 = _a - _b;                                            \
    float _c = (d4) - (d2), _e = 2.f*((d3) - (d1));                        \
    o3 = _c + _e; o4 = _c - _e;                                            \
    o5 = 4.f*(d1) - 5.f*(d3) + (d5);                                       \
} while (0)

#define ATCOMB(m0,m1,m2,m3,m4,m5,o0,o1,o2,o3) do {                         \
    float _s = (m1)+(m2), _d = (m1)-(m2), _t = (m3)+(m4), _u = (m3)-(m4);  \
    o0 = (m0) + _s + _t;                                                   \
    o1 = _d + 2.f*_u;                                                      \
    o2 = _s + 4.f*_t;                                                      \
    o3 = _d + 8.f*_u + (m5);                                               \
} while (0)

#define GCOMB(w0,w1,w2,o0,o1,o2,o3,o4,o5) do {                             \
    o0 = 0.25f*(w0);                                                       \
    float _n = -(w0) - (w2);                                               \
    o1 = (_n - (w1)) * (1.f/6.f);                                          \
    o2 = (_n + (w1)) * (1.f/6.f);                                          \
    float _p = (w0)*(1.f/24.f) + (w2)*(1.f/6.f), _q = (w1)*(1.f/12.f);     \
    o3 = _p + _q; o4 = _p - _q;                                            \
    o5 = (w2);                                                             \
} while (0)

__device__ __forceinline__ void bf16_split(float v, __nv_bfloat16& h,
                                           __nv_bfloat16& l) {
    h = __float2bfloat16(v);
    l = __float2bfloat16(v - __bfloat162float(h));
}

// ---------------------------------------------------------------------------
// Filter transform -> bf16 hi/lo planes, layout [set][pos][oc][ic]
// ---------------------------------------------------------------------------
__global__ __launch_bounds__(256) void wino_filt3(
    const float* __restrict__ W0, const float* __restrict__ W1,
    const float* __restrict__ W2, __nv_bfloat16* __restrict__ Uh)
{
    __nv_bfloat16* Ul = Uh + 3ull * 36 * 16384;
    int idx = blockIdx.x * 256 + threadIdx.x;
    if (idx >= 3 * 16384) return;
    int set = idx >> 14, e = idx & 16383;
    int oc = e & 127, ic = e >> 7;
    const float* W = (set == 0) ? W0 : (set == 1) ? W1 : W2;
    size_t soff = (size_t)set * (36 * 16384);
    float w[3][3];
#pragma unroll
    for (int a = 0; a < 3; ++a)
#pragma unroll
        for (int b = 0; b < 3; ++b)
            w[a][b] = W[(size_t)oc * 1152 + ic * 9 + a * 3 + b];
    float ee[6][3];
#pragma unroll
    for (int b = 0; b < 3; ++b)
        GCOMB(w[0][b], w[1][b], w[2][b],
              ee[0][b], ee[1][b], ee[2][b], ee[3][b], ee[4][b], ee[5][b]);
#pragma unroll
    for (int i = 0; i < 6; ++i) {
        float u[6];
        GCOMB(ee[i][0], ee[i][1], ee[i][2], u[0], u[1], u[2], u[3], u[4], u[5]);
#pragma unroll
        for (int j = 0; j < 6; ++j) {
            size_t off = soff + (size_t)(i * 6 + j) * 16384 + oc * 128 + ic;
            __nv_bfloat16 h, l;
            bf16_split(u[j], h, l);
            Uh[off] = h; Ul[off] = l;
        }
    }
}

// ---------------------------------------------------------------------------
// Merged input transform -> bf16 hi/lo V planes [img][pos][ic][tile]
// ---------------------------------------------------------------------------
__global__ __launch_bounds__(256) void wino_in14(
    const float* __restrict__ xq, const float* __restrict__ xkv,
    const float* __restrict__ xkvw, __nv_bfloat16* __restrict__ vh)
{
    __nv_bfloat16* vl = vh + 14ull * VIMG;
    __shared__ __align__(16) float s_d[4][6][264];
    int img = blockIdx.z, ty = blockIdx.y, c4 = blockIdx.x;
    int tid = threadIdx.x;
    const float* xb;
    if (img < 2)      xb = xq   + (size_t)img * IMG;
    else if (img < 6) xb = xkv  + (size_t)(img - 2) * IMG;
    else              xb = xkvw + (size_t)(img - 6) * IMG;
    xb += (size_t)(c4 * 4) * HWSZ;

    for (int i = tid; i < 4 * 6 * 258; i += 256) {
        int c = i / (6 * 258);
        int rem = i - c * (6 * 258);
        int r = rem / 258, col = rem - r * 258;
        int gy = ty * 4 - 1 + r, gx = col - 1;
        float v = 0.f;
        if ((unsigned)gy < 256u && (unsigned)gx < 256u)
            v = xb[(size_t)c * HWSZ + gy * 256 + gx];
        s_d[c][r][col] = v;
    }
    __syncthreads();

    int tx = tid & 63, c = tid >> 6;
    float d[6][6];
#pragma unroll
    for (int r = 0; r < 6; ++r) {
        const float4* row = (const float4*)s_d[c][r];
        float4 a = row[tx], b = row[tx + 1];
        d[r][0] = a.x; d[r][1] = a.y; d[r][2] = a.z;
        d[r][3] = a.w; d[r][4] = b.x; d[r][5] = b.y;
    }
    float e[6][6];
#pragma unroll
    for (int j = 0; j < 6; ++j)
        BTCOMB(d[0][j], d[1][j], d[2][j], d[3][j], d[4][j], d[5][j],
               e[0][j], e[1][j], e[2][j], e[3][j], e[4][j], e[5][j]);

    size_t base = (size_t)img * VIMG + (size_t)(c4 * 4 + c) * 4096 +
                  ty * 64 + tx;
#pragma unroll
    for (int i = 0; i < 6; ++i) {
        float o[6];
        BTCOMB(e[i][0], e[i][1], e[i][2], e[i][3], e[i][4], e[i][5],
               o[0], o[1], o[2], o[3], o[4], o[5]);
#pragma unroll
        for (int j = 0; j < 6; ++j) {
            size_t off = base + (size_t)(i * 6 + j) * 524288;
            __nv_bfloat16 h, l;
            bf16_split(o[j], h, l);
            vh[off] = h; vl[off] = l;
        }
    }
}

// FF-stage input transform (2 images from gQ)
__global__ __launch_bounds__(256) void wino_in(
    const float* __restrict__ x, __nv_bfloat16* __restrict__ vh)
{
    __nv_bfloat16* vl = vh + 14ull * VIMG;
    __shared__ __align__(16) float s_d[4][6][264];
    int img = blockIdx.z, ty = blockIdx.y, c4 = blockIdx.x;
    int tid = threadIdx.x;
    const float* xb = x + (size_t)img * IMG + (size_t)(c4 * 4) * HWSZ;

    for (int i = tid; i < 4 * 6 * 258; i += 256) {
        int c = i / (6 * 258);
        int rem = i - c * (6 * 258);
        int r = rem / 258, col = rem - r * 258;
        int gy = ty * 4 - 1 + r, gx = col - 1;
        float v = 0.f;
        if ((unsigned)gy < 256u && (unsigned)gx < 256u)
            v = xb[(size_t)c * HWSZ + gy * 256 + gx];
        s_d[c][r][col] = v;
    }
    __syncthreads();

    int tx = tid & 63, c = tid >> 6;
    float d[6][6];
#pragma unroll
    for (int r = 0; r < 6; ++r) {
        const float4* row = (const float4*)s_d[c][r];
        float4 a = row[tx], b = row[tx + 1];
        d[r][0] = a.x; d[r][1] = a.y; d[r][2] = a.z;
        d[r][3] = a.w; d[r][4] = b.x; d[r][5] = b.y;
    }
    float e[6][6];
#pragma unroll
    for (int j = 0; j < 6; ++j)
        BTCOMB(d[0][j], d[1][j], d[2][j], d[3][j], d[4][j], d[5][j],
               e[0][j], e[1][j], e[2][j], e[3][j], e[4][j], e[5][j]);

    size_t base = (size_t)img * VIMG + (size_t)(c4 * 4 + c) * 4096 +
                  ty * 64 + tx;
#pragma unroll
    for (int i = 0; i < 6; ++i) {
        float o[6];
        BTCOMB(e[i][0], e[i][1], e[i][2], e[i][3], e[i][4], e[i][5],
               o[0], o[1], o[2], o[3], o[4], o[5]);
#pragma unroll
        for (int j = 0; j < 6; ++j) {
            size_t off = base + (size_t)(i * 6 + j) * 524288;
            __nv_bfloat16 h, l;
            bf16_split(o[j], h, l);
            vh[off] = h; vl[off] = l;
        }
    }
}

// ---------------------------------------------------------------------------
// Winograd GEMM via mma.sync (HMMA) + bf16 3-term split.
// Block = 128 oc x 128 tiles; 8 warps (2m x 4n); warp = 64 oc x 32 tiles.
// K = 128 ic in 4 chunks of 32, cp.async double-buffered.
// smem: As[2 st][2 term][128 oc rows, 80B padded], Bs[2][2][32 ic rows, 272B].
// ---------------------------------------------------------------------------
#define GEMM_SMEM 75776
#define AS_STAGE 20480
#define AS_TERM  10240
#define BS_BASE  40960
#define BS_STAGE 17408
#define BS_TERM  8704

__global__ __launch_bounds__(256, 1) void wino_gemm_mma(
    const __nv_bfloat16* __restrict__ vh, const __nv_bfloat16* __restrict__ uh,
    float* __restrict__ mout, int route)
{
    extern __shared__ __align__(16) char smx[];
    const __nv_bfloat16* vl = vh + 14ull * VIMG;
    const __nv_bfloat16* ul = uh + 3ull * 36 * 16384;

    int pos = blockIdx.y, img = blockIdx.z, tb = blockIdx.x;
    int tid = threadIdx.x, l = tid & 31, wid = tid >> 5;
    int warp_m = wid & 1, warp_n = wid >> 1;

    int uset = route ? ((img < 2) ? 0 : 1) : 2;
    size_t uoff = (size_t)uset * (36 * 16384) + (size_t)pos * 16384;
    size_t voff = (size_t)img * VIMG + (size_t)pos * 524288 + tb * 128;

    uint32_t sb = smem_u32(smx);

#define COPY_CHUNK(chunk, buf) do {                                         \
    int _ic0 = (chunk) * 32;                                                \
    _Pragma("unroll")                                                       \
    for (int _i = 0; _i < 4; ++_i) {                                        \
        int _t = tid + _i * 256;                                            \
        /* A: term, row(128), seg(4 x 16B) */                               \
        int _term = _t >> 9, _r = (_t >> 2) & 127, _s = _t & 3;             \
        const __nv_bfloat16* _src =                                         \
            (_term ? ul : uh) + uoff + _r * 128 + _ic0 + _s * 8;            \
        cp16(sb + (buf) * AS_STAGE + _term * AS_TERM + _r * 80 + _s * 16,   \
             _src);                                                         \
        /* B: term, row(32), seg(16 x 16B) */                               \
        int _bt = _t >> 9, _rem = _t & 511, _br = _rem >> 4, _bs = _rem & 15;\
        const __nv_bfloat16* _bsrc =                                        \
            (_bt ? vl : vh) + voff + (size_t)(_ic0 + _br) * 4096 + _bs * 8; \
        cp16(sb + BS_BASE + (buf) * BS_STAGE + _bt * BS_TERM +              \
             _br * 272 + _bs * 16, _bsrc);                                  \
    }                                                                       \
    CP_COMMIT();                                                            \
} while (0)

    float d[4][4][4];
#pragma unroll
    for (int mt = 0; mt < 4; ++mt)
#pragma unroll
        for (int nt = 0; nt < 4; ++nt)
#pragma unroll
            for (int k = 0; k < 4; ++k) d[mt][nt][k] = 0.f;

    COPY_CHUNK(0, 0);

    for (int c = 0; c < 4; ++c) {
        int buf = c & 1;
        if (c < 3) {
            COPY_CHUNK(c + 1, buf ^ 1);
            CP_WAIT(1);
        } else {
            CP_WAIT(0);
        }
        __syncthreads();

#pragma unroll
        for (int ks = 0; ks < 2; ++ks) {
            uint32_t ah[4][4], al[4][4], bh[2][4], bl[2][4];
#pragma unroll
            for (int mt = 0; mt < 4; ++mt) {
                uint32_t aa = sb + buf * AS_STAGE +
                    (warp_m * 64 + mt * 16 + (l & 15)) * 80 +
                    ks * 32 + (l >> 4) * 16;
                ldsm4(ah[mt], aa);
                ldsm4(al[mt], aa + AS_TERM);
            }
#pragma unroll
            for (int n2 = 0; n2 < 2; ++n2) {
                uint32_t ba = sb + BS_BASE + buf * BS_STAGE +
                    (ks * 16 + (l & 7) + ((l >> 3) & 1) * 8) * 272 +
                    (warp_n * 32 + n2 * 16) * 2 + (l >> 4) * 16;
                ldsm4t(bh[n2], ba);
                ldsm4t(bl[n2], ba + BS_TERM);
            }
            // term 1: Ah x Bh
#pragma unroll
            for (int mt = 0; mt < 4; ++mt)
#pragma unroll
                for (int nt = 0; nt < 4; ++nt)
                    mma_bf16(d[mt][nt], ah[mt],
                             bh[nt >> 1][(nt & 1) * 2], bh[nt >> 1][(nt & 1) * 2 + 1]);
            // term 2: Al x Bh
#pragma unroll
            for (int mt = 0; mt < 4; ++mt)
#pragma unroll
                for (int nt = 0; nt < 4; ++nt)
                    mma_bf16(d[mt][nt], al[mt],
                             bh[nt >> 1][(nt & 1) * 2], bh[nt >> 1][(nt & 1) * 2 + 1]);
            // term 3: Ah x Bl
#pragma unroll
            for (int mt = 0; mt < 4; ++mt)
#pragma unroll
                for (int nt = 0; nt < 4; ++nt)
                    mma_bf16(d[mt][nt], ah[mt],
                             bl[nt >> 1][(nt & 1) * 2], bl[nt >> 1][(nt & 1) * 2 + 1]);
        }
        __syncthreads();
    }

    float* Mo = mout + (size_t)img * VIMG + (size_t)pos * 524288 + tb * 128;
#pragma unroll
    for (int mt = 0; mt < 4; ++mt)
#pragma unroll
        for (int nt = 0; nt < 4; ++nt) {
            int oc0 = warp_m * 64 + mt * 16 + (l >> 2);
            int t0  = warp_n * 32 + nt * 8 + (l & 3) * 2;
            float2 v01 = make_float2(d[mt][nt][0], d[mt][nt][1]);
            float2 v23 = make_float2(d[mt][nt][2], d[mt][nt][3]);
            *(float2*)(Mo + (size_t)oc0 * 4096 + t0) = v01;
            *(float2*)(Mo + (size_t)(oc0 + 8) * 4096 + t0) = v23;
        }
#undef COPY_CHUNK
}

// ---------------------------------------------------------------------------
// Merged output transform + bias + PReLU + residual, per-image routing.
// ---------------------------------------------------------------------------
__global__ __launch_bounds__(256) void wino_out14(
    const float* __restrict__ mout,
    const float* __restrict__ r0, const float* __restrict__ r1,
    const float* __restrict__ r2,
    float* __restrict__ y0, float* __restrict__ y1, float* __restrict__ y2,
    const float* __restrict__ bias0, const float* __restrict__ alpha0,
    const float* __restrict__ bias1, const float* __restrict__ alpha1,
    int route)
{
    __shared__ __align__(16) float s_o[8][4][256];
    int img = blockIdx.z, ty = blockIdx.y, og = blockIdx.x;
    int tid = threadIdx.x;

    const float* resid; float* y; const float* bias; const float* alpha;
    if (!route || img < 2) {
        resid = r0 + (size_t)img * IMG; y = y0 + (size_t)img * IMG;
        bias = bias0; alpha = alpha0;
    } else if (img < 6) {
        resid = r1 + (size_t)(img - 2) * IMG; y = y1 + (size_t)(img - 2) * IMG;
        bias = bias1; alpha = alpha1;
    } else {
        resid = r2 + (size_t)(img - 6) * IMG; y = y2 + (size_t)(img - 6) * IMG;
        bias = bias1; alpha = alpha1;
    }

#pragma unroll
    for (int it = 0; it < 2; ++it) {
        int item = tid + it * 256;
        int tx = item & 63, ol = item >> 6;
        const float* Mp = mout + (size_t)img * VIMG +
                          (size_t)(og * 8 + ol) * 4096 + ty * 64 + tx;
        float m[6][6];
#pragma unroll
        for (int pos = 0; pos < 36; ++pos)
            m[pos / 6][pos % 6] = Mp[(size_t)pos * 524288];
        float e[4][6];
#pragma unroll
        for (int j = 0; j < 6; ++j)
            ATCOMB(m[0][j], m[1][j], m[2][j], m[3][j], m[4][j], m[5][j],
                   e[0][j], e[1][j], e[2][j], e[3][j]);
#pragma unroll
        for (int r = 0; r < 4; ++r) {
            float o0, o1, o2, o3;
            ATCOMB(e[r][0], e[r][1], e[r][2], e[r][3], e[r][4], e[r][5],
                   o0, o1, o2, o3);
            ((float4*)s_o[ol][r])[tx] = make_float4(o0, o1, o2, o3);
        }
    }
    __syncthreads();

    float a = alpha[0];
    for (int i = tid; i < 8192; i += 256) {
        int ol = i >> 10, rem = i & 1023, r = rem >> 8, px = rem & 255;
        int oc = og * 8 + ol;
        int gy = ty * 4 + r;
        size_t addr = (size_t)oc * HWSZ + gy * 256 + px;
        float v = s_o[ol][r][px] + bias[oc];
        v = (v >= 0.f) ? v : a * v;
        y[addr] = resid[addr] + v;
    }
}

// ---------------------------------------------------------------------------
// Windowed dual-branch attention (register-blocked; pre-dup K/V variant)
// ---------------------------------------------------------------------------
#define QST 66
#define KDST 385
#define PST 66
#define VDST 129
#define OST 66
#define OFF_KD 8448
#define OFF_SV2 25344
#define OFF_SM 41856
#define ATTN_SMEM 167680
#define NK 384

__global__ __launch_bounds__(256) void win_attn(
    float* __restrict__ Qbuf, const float* __restrict__ KV,
    const float* __restrict__ KVw, const float* __restrict__ em)
{
    extern __shared__ __align__(16) float sm[];
    float* s_q = sm;
    unsigned long long* s_kd = (unsigned long long*)(sm + OFF_KD);
    float* s_p = sm;
    unsigned long long* s_v2 = (unsigned long long*)(sm + OFF_SV2);
    float* s_m = sm + OFF_SM;

    int bwin = blockIdx.x;
    int bb  = bwin >> 10;
    int wy8 = ((bwin >> 5) & 31) << 3;
    int wx8 = (bwin & 31) << 3;
    int tid = threadIdx.x;
    int qb = tid >> 5;
    int kidx = tid & 31;

    float* qimg = Qbuf + (size_t)bb * IMG;
    const float* kv0 = KV + (size_t)bb * 2 * IMG;
    const float* kv1 = KVw + (size_t)bb * 4 * IMG;

    for (int i = tid; i < 64 * CC; i += 256) {
        int q = i & 63, c = i >> 6;
        int gy = wy8 + (q >> 3), gx = wx8 + (q & 7);
        s_q[c * QST + q] = qimg[(size_t)c * HWSZ + gy * WW + gx];
    }
    if (tid < 64) {
        int gy = wy8 + (tid >> 3), gx = wx8 + (tid & 7);
        s_m[tid] = em[(size_t)bb * HWSZ + gy * WW + gx];
    }

    unsigned long long accs[4][12];
#pragma unroll
    for (int p = 0; p < 4; ++p)
#pragma unroll
        for (int j = 0; j < 12; ++j) accs[p][j] = 0ull;

    for (int c0 = 0; c0 < 128; c0 += 32) {
        __syncthreads();
        for (int i = tid; i < 32 * NK; i += 256) {
            int k = i % NK, c2 = i / NK;
            const float* base;
            int t;
            if (k < 128) { base = kv0 + (size_t)(k >> 6) * IMG; t = k & 63; }
            else { int kk = k - 128; base = kv1 + (size_t)(kk >> 6) * IMG; t = kk & 63; }
            int gy = wy8 + (t >> 3), gx = wx8 + (t & 7);
            float kvv = base[(size_t)(c0 + c2) * HWSZ + gy * WW + gx];
            s_kd[c2 * KDST + k] = pack2(kvv, kvv);
        }
        __syncthreads();

#pragma unroll 2
        for (int c2 = 0; c2 < 32; ++c2) {
            const unsigned long long* qsrc =
                (const unsigned long long*)(s_q + (c0 + c2) * QST + qb * 8);
            unsigned long long qp0 = qsrc[0], qp1 = qsrc[1],
                               qp2 = qsrc[2], qp3 = qsrc[3];
            const unsigned long long* krow = s_kd + c2 * KDST + kidx;
#pragma unroll
            for (int j = 0; j < 12; ++j) {
                unsigned long long k2 = krow[32 * j];
                ffma2(accs[0][j], qp0, k2);
                ffma2(accs[1][j], qp1, k2);
                ffma2(accs[2][j], qp2, k2);
                ffma2(accs[3][j], qp3, k2);
            }
        }
    }

    float sreg[8][12];
#pragma unroll
    for (int p = 0; p < 4; ++p)
#pragma unroll
        for (int j = 0; j < 12; ++j)
            unpack2(accs[p][j], sreg[2 * p][j], sreg[2 * p + 1][j]);

    const float SCALE = 0.08838834764831845f;
#pragma unroll
    for (int r = 0; r < 8; ++r) {
        float msk = s_m[qb * 8 + r];
        {
            float m = sreg[r][0];
#pragma unroll
            for (int j = 1; j < 4; ++j) m = fmaxf(m, sreg[r][j]);
#pragma unroll
            for (int off = 16; off >= 1; off >>= 1)
                m = fmaxf(m, __shfl_xor_sync(0xffffffffu, m, off));
            m *= SCALE;
            float sum = 0.f;
#pragma unroll
            for (int j = 0; j < 4; ++j) {
                float e = __expf(sreg[r][j] * SCALE - m);
                sreg[r][j] = e; sum += e;
            }
#pragma unroll
            for (int off = 16; off >= 1; off >>= 1)
                sum += __shfl_xor_sync(0xffffffffu, sum, off);
            float inv = msk / sum;
#pragma unroll
            for (int j = 0; j < 4; ++j) sreg[r][j] *= inv;
        }
        {
            float m = sreg[r][4];
#pragma unroll
            for (int j = 5; j < 12; ++j) m = fmaxf(m, sreg[r][j]);
#pragma unroll
            for (int off = 16; off >= 1; off >>= 1)
                m = fmaxf(m, __shfl_xor_sync(0xffffffffu, m, off));
            m *= SCALE;
            float sum = 0.f;
#pragma unroll
            for (int j = 4; j < 12; ++j) {
                float e = __expf(sreg[r][j] * SCALE - m);
                sreg[r][j] = e; sum += e;
            }
#pragma unroll
            for (int off = 16; off >= 1; off >>= 1)
                sum += __shfl_xor_sync(0xffffffffu, sum, off);
            float inv = (1.f - msk) / sum;
#pragma unroll
            for (int j = 4; j < 12; ++j) sreg[r][j] *= inv;
        }
    }

    __syncthreads();
#pragma unroll
    for (int j = 0; j < 12; ++j) {
        int k = kidx + 32 * j;
#pragma unroll
        for (int p = 0; p < 4; ++p)
            *(unsigned long long*)(s_p + k * PST + qb * 8 + 2 * p) =
                pack2(sreg[2 * p][j], sreg[2 * p + 1][j]);
    }

    unsigned long long oacc[4][4];
#pragma unroll
    for (int p = 0; p < 4; ++p)
#pragma unroll
        for (int jc = 0; jc < 4; ++jc) oacc[p][jc] = 0ull;

    for (int kc = 0; kc < 6; ++kc) {
        __syncthreads();
        for (int i = tid; i < 64 * CC; i += 256) {
            int kk = i & 63, c = i >> 6;
            int k = kc * 64 + kk;
            const float* base;
            if (k < 128) base = kv0 + (size_t)(k >> 6) * IMG;
            else         base = kv1 + (size_t)((k - 128) >> 6) * IMG;
            int gy = wy8 + (kk >> 3), gx = wx8 + (kk & 7);
            float vv = base[(size_t)c * HWSZ + gy * WW + gx];
            s_v2[kk * VDST + c] = pack2(vv, vv);
        }
        __syncthreads();

#pragma unroll 2
        for (int kk = 0; kk < 64; ++kk) {
            int k = kc * 64 + kk;
            const unsigned long long* pp =
                (const unsigned long long*)(s_p + k * PST + qb * 8);
            unsigned long long p0 = pp[0], p1 = pp[1], p2 = pp[2], p3 = pp[3];
            const unsigned long long* vrow = s_v2 + kk * VDST + kidx;
#pragma unroll
            for (int jc = 0; jc < 4; ++jc) {
                unsigned long long v2 = vrow[32 * jc];
                ffma2(oacc[0][jc], p0, v2);
                ffma2(oacc[1][jc], p1, v2);
                ffma2(oacc[2][jc], p2, v2);
                ffma2(oacc[3][jc], p3, v2);
            }
        }
    }

    __syncthreads();
    float* s_o = sm;
#pragma unroll
    for (int jc = 0; jc < 4; ++jc) {
        int c = kidx + 32 * jc;
#pragma unroll
        for (int p = 0; p < 4; ++p)
            *(unsigned long long*)(s_o + c * OST + qb * 8 + 2 * p) = oacc[p][jc];
    }
    __syncthreads();
    for (int i = tid; i < 64 * CC; i += 256) {
        int q = i & 63, c = i >> 6;
        int gy = wy8 + (q >> 3), gx = wx8 + (q & 7);
        qimg[(size_t)c * HWSZ + gy * WW + gx] += s_o[c * OST + q];
    }
}

// ---------------------------------------------------------------------------
extern "C" void kernel_launch(void* const* d_in, const int* in_sizes, int n_in,
                              void* d_out, int out_size)
{
    const float* xq   = (const float*)d_in[0];
    const float* xkvw = (const float*)d_in[1];
    const float* xkv  = (const float*)d_in[2];
    const float* em   = (const float*)d_in[3];
    const float* Wq   = (const float*)d_in[4];
    const float* bq   = (const float*)d_in[5];
    const float* aq   = (const float*)d_in[6];
    const float* Wkv  = (const float*)d_in[7];
    const float* bkv  = (const float*)d_in[8];
    const float* akv  = (const float*)d_in[9];
    const float* Wff  = (const float*)d_in[10];
    const float* bff  = (const float*)d_in[11];
    const float* aff  = (const float*)d_in[12];
    float* out = (float*)d_out;

    float *gQ = nullptr, *gKV = nullptr, *gKVw = nullptr;
    float *gV = nullptr, *gM = nullptr, *gU = nullptr;
    cudaGetSymbolAddress((void**)&gQ,   g_Q);
    cudaGetSymbolAddress((void**)&gKV,  g_KV);
    cudaGetSymbolAddress((void**)&gKVw, g_KVw);
    cudaGetSymbolAddress((void**)&gV,   g_V);
    cudaGetSymbolAddress((void**)&gM,   g_M);
    cudaGetSymbolAddress((void**)&gU,   g_U);

    __nv_bfloat16* gVh = (__nv_bfloat16*)gV;
    __nv_bfloat16* gUh = (__nv_bfloat16*)gU;

    cudaFuncSetAttribute(win_attn, cudaFuncAttributeMaxDynamicSharedMemorySize,
                         ATTN_SMEM);
    cudaFuncSetAttribute(wino_gemm_mma,
                         cudaFuncAttributeMaxDynamicSharedMemorySize, GEMM_SMEM);

    dim3 blk(256);

    wino_filt3<<<192, blk>>>(Wq, Wkv, Wff, gUh);

    wino_in14<<<dim3(32, 64, 14), blk>>>(xq, xkv, xkvw, gVh);
    wino_gemm_mma<<<dim3(32, 36, 14), blk, GEMM_SMEM>>>(gVh, gUh, gM, 1);
    wino_out14<<<dim3(16, 64, 14), blk>>>(gM, xq, xkv, xkvw, gQ, gKV, gKVw,
                                          bq, aq, bkv, akv, 1);

    win_attn<<<2048, blk, ATTN_SMEM>>>(gQ, gKV, gKVw, em);

    wino_in<<<dim3(32, 64, 2), blk>>>(gQ, gVh);
    wino_gemm_mma<<<dim3(32, 36, 2), blk, GEMM_SMEM>>>(gVh, gUh, gM, 0);
    wino_out14<<<dim3(16, 64, 2), blk>>>(gM, gQ, gQ, gQ, out, out, out,
                                         bff, aff, bff, aff, 0);
}